// round 6
// baseline (speedup 1.0000x reference)
#include <cuda_runtime.h>
#include <cstdint>

// Problem constants (shapes fixed by the dataset)
#define SQ 50          // qubits
#define SP 3           // pauli basis
#define SS 64          // heads
#define WORDS 256      // pauli words per block
#define THREADS 1024   // 32 warps; warp octets split 64 heads, 2 words/thread
#define TROW 156       // padded row stride (LDS.128 phase-conflict-free)

// Packed heads: ha[q][j(32 pairs)][4] = {h0s0,h0s1,h1s0,h1s1}; hc[q][j][2] = {h2s0,h2s1}
#define HA_TOTAL (SQ * 128)   // 6400 floats
#define HC_TOTAL (SQ * 64)    // 3200 floats

// smem float offsets
#define OFF_HC   HA_TOTAL                  // 6400
#define OFF_HR   (OFF_HC + HC_TOTAL)       // 9600
#define OFF_PART (OFF_HR + SS)             // 9664  (7 * 256 floats)
#define OFF_RED  (OFF_PART + 7 * WORDS)    // 11456 (8 floats = 4 doubles; 8B aligned)
#define OFF_T    (OFF_RED + 8)             // 11464 (byte offset 45856, 16B aligned)
#define SMEM_FLOATS (OFF_T + WORDS * TROW)

__device__ double       g_accum;
__device__ unsigned int g_count;
__device__ float        g_ha[HA_TOTAL];
__device__ float        g_hc[HC_TOTAL];
__device__ float        g_hr[SS];

__device__ __forceinline__ float softplus20(float x) {
    float y = x * 20.0f;
    return fmaxf(y, 0.0f) + log1pf(expf(-fabsf(y)));
}

// ---------------------------------------------------------------------------
__global__ void prep_kernel(const float* __restrict__ heads_param,
                            const float* __restrict__ hr_param) {
    const int tid = threadIdx.x;

    if (blockIdx.x == 0 && tid == 0) { g_accum = 0.0; g_count = 0u; }

    __shared__ float s_hr[SS];
    if (tid < SS) s_hr[tid] = softplus20(hr_param[tid]);
    __syncthreads();
    if (blockIdx.x == 0 && tid < SS) {
        float s = 0.0f;
        #pragma unroll
        for (int i = 0; i < SS; i++) s += s_hr[i];
        s = fmaxf(s, 1e-12f);
        g_hr[tid] = (s_hr[tid] / s + 0.001f / (float)SS) / 1.001f;
    }

    const int stride = blockDim.x * gridDim.x;
    for (int i = blockIdx.x * blockDim.x + tid; i < SS * SQ; i += stride) {
        int s = i / SQ;
        int q = i - s * SQ;
        const float* hp = heads_param + (s * SQ + q) * SP;
        float h0 = softplus20(hp[0]);
        float h1 = softplus20(hp[1]);
        float h2 = softplus20(hp[2]);
        float inv = 1.0f / fmaxf(h0 + h1 + h2, 1e-12f);
        h0 *= inv; h1 *= inv; h2 *= inv;
        int j = s >> 1, o = s & 1;
        g_ha[q * 128 + j * 4 + 0 + o] = h0;
        g_ha[q * 128 + j * 4 + 2 + o] = h1;
        g_hc[q * 64  + j * 2 + o]     = h2;
    }
}

// ---------------------------------------------------------------------------
// Per-q step for 2 words x 4 head-pairs.
// dot = t2c * (h2 + h0*(t0/t2c) + h1*(t1/t2c)); all-nonneg inner sums.
// ---------------------------------------------------------------------------
__device__ __forceinline__ void proc_q2(
    int qi,
    float t0a, float t1a, float t2a,     // word A
    float t0b, float t1b, float t2b,     // word B
    const float* __restrict__ sh_ha_e,   // sh_ha + eighth*16
    const float* __restrict__ sh_hc_e,   // sh_hc + eighth*8
    uint64_t* __restrict__ accA, uint64_t* __restrict__ accB,
    float& pAa, float& pAb, float& pBa, float& pBb)
{
    float t2ca = fmaxf(t2a, 1e-12f);
    float t2cb = fmaxf(t2b, 1e-12f);
    float ra, rb;
    asm("rcp.approx.f32 %0, %1;" : "=f"(ra) : "f"(t2ca));
    asm("rcp.approx.f32 %0, %1;" : "=f"(rb) : "f"(t2cb));
    float r0a = t0a * ra, r1a = t1a * ra;
    float r0b = t0b * rb, r1b = t1b * rb;
    if (qi < SQ / 2) { pAa *= t2ca; pBa *= t2cb; }
    else             { pAb *= t2ca; pBb *= t2cb; }

    uint64_t R0A, R1A, R0B, R1B;
    asm("mov.b64 %0, {%1, %2};" : "=l"(R0A) : "f"(r0a), "f"(r0a));
    asm("mov.b64 %0, {%1, %2};" : "=l"(R1A) : "f"(r1a), "f"(r1a));
    asm("mov.b64 %0, {%1, %2};" : "=l"(R0B) : "f"(r0b), "f"(r0b));
    asm("mov.b64 %0, {%1, %2};" : "=l"(R1B) : "f"(r1b), "f"(r1b));

    const ulonglong2* ha = (const ulonglong2*)(sh_ha_e + qi * 128);
    const uint64_t*   hc = (const uint64_t*)  (sh_hc_e + qi * 64);
    #pragma unroll
    for (int j = 0; j < 4; j++) {
        ulonglong2 Ha = ha[j];     // {(h0 s0,s1), (h1 s0,s1)} 16B
        uint64_t   Hc = hc[j];     // (h2 s0,s1) 8B
        uint64_t dA, dB;
        asm("fma.rn.f32x2 %0, %1, %2, %3;" : "=l"(dA) : "l"(Ha.x), "l"(R0A), "l"(Hc));
        asm("fma.rn.f32x2 %0, %1, %2, %3;" : "=l"(dB) : "l"(Ha.x), "l"(R0B), "l"(Hc));
        asm("fma.rn.f32x2 %0, %1, %2, %3;" : "=l"(dA) : "l"(Ha.y), "l"(R1A), "l"(dA));
        asm("fma.rn.f32x2 %0, %1, %2, %3;" : "=l"(dB) : "l"(Ha.y), "l"(R1B), "l"(dB));
        asm("mul.rn.f32x2 %0, %1, %2;"     : "=l"(accA[j]) : "l"(accA[j]), "l"(dA));
        asm("mul.rn.f32x2 %0, %1, %2;"     : "=l"(accB[j]) : "l"(accB[j]), "l"(dB));
    }
}

// ---------------------------------------------------------------------------
// Main: warp octet g=wid>>3 covers words [g*64, g*64+64); eighth = wid&7
// handles head pairs eighth*4..eighth*4+3. Thread words: lane, lane+32.
// ---------------------------------------------------------------------------
__global__ void __launch_bounds__(THREADS, 1)
main_kernel(const float* __restrict__ pauli,
            const float* __restrict__ coeff,
            float* __restrict__ out,
            int N, int nblocks) {
    extern __shared__ float smem[];
    float*  sh_ha   = smem;
    float*  sh_hc   = smem + OFF_HC;
    float*  sh_hr   = smem + OFF_HR;
    float*  sh_part = smem + OFF_PART;
    double* sh_red  = (double*)(smem + OFF_RED);
    float*  sh_t    = smem + OFF_T;

    const int tid  = threadIdx.x;
    const int wid  = tid >> 5;
    const int lane = tid & 31;

    // Stage packed heads
    {
        const float4* src = (const float4*)g_ha;
        float4*       dst = (float4*)sh_ha;
        #pragma unroll
        for (int i = tid; i < HA_TOTAL / 4; i += THREADS) dst[i] = src[i];
        const float4* src2 = (const float4*)g_hc;
        float4*       dst2 = (float4*)sh_hc;
        #pragma unroll
        for (int i = tid; i < HC_TOTAL / 4; i += THREADS) dst2[i] = src2[i];
    }
    if (tid < SS) sh_hr[tid] = g_hr[tid];

    // Stage pauli tile: coalesced global reads, padded-row scatter
    const int base  = blockIdx.x * WORDS;
    const int valid = min(WORDS, N - base);
    const int total = valid * (SQ * SP);
    const float* gsrc = pauli + (size_t)base * (SQ * SP);
    for (int f = tid; f < total; f += THREADS) {
        int row = f / (SQ * SP);
        int col = f - row * (SQ * SP);
        sh_t[row * TROW + col] = gsrc[f];
    }
    __syncthreads();

    const int eighth = wid & 7;
    const int group  = wid >> 3;
    const int wA = group * 64 + lane;        // word A (local)
    const int wB = wA + 32;                  // word B (local)
    const float* trowA = sh_t + wA * TROW;
    const float* trowB = sh_t + wB * TROW;
    const float* sh_ha_e = sh_ha + eighth * 16;   // 4 pairs * 4 floats
    const float* sh_hc_e = sh_hc + eighth * 8;    // 4 pairs * 2 floats

    uint64_t accA[4], accB[4];
    #pragma unroll
    for (int j = 0; j < 4; j++) { accA[j] = 0x3F8000003F800000ull; accB[j] = accA[j]; }
    float pAa = 1.0f, pAb = 1.0f, pBa = 1.0f, pBb = 1.0f;

    const float4* tvA = (const float4*)trowA;
    const float4* tvB = (const float4*)trowB;
    #pragma unroll 1
    for (int c = 0; c < 12; c++) {
        float4 A0 = tvA[3 * c + 0], A1 = tvA[3 * c + 1], A2 = tvA[3 * c + 2];
        float4 B0 = tvB[3 * c + 0], B1 = tvB[3 * c + 1], B2 = tvB[3 * c + 2];
        proc_q2(4 * c + 0, A0.x, A0.y, A0.z, B0.x, B0.y, B0.z, sh_ha_e, sh_hc_e, accA, accB, pAa, pAb, pBa, pBb);
        proc_q2(4 * c + 1, A0.w, A1.x, A1.y, B0.w, B1.x, B1.y, sh_ha_e, sh_hc_e, accA, accB, pAa, pAb, pBa, pBb);
        proc_q2(4 * c + 2, A1.z, A1.w, A2.x, B1.z, B1.w, B2.x, sh_ha_e, sh_hc_e, accA, accB, pAa, pAb, pBa, pBb);
        proc_q2(4 * c + 3, A2.y, A2.z, A2.w, B2.y, B2.z, B2.w, sh_ha_e, sh_hc_e, accA, accB, pAa, pAb, pBa, pBb);
    }
    {   // q = 48, 49 (cols 144..149, 8B-aligned)
        const float2* a2 = (const float2*)(trowA + 144);
        const float2* b2 = (const float2*)(trowB + 144);
        float2 ua = a2[0], va = a2[1], wa = a2[2];
        float2 ub = b2[0], vb = b2[1], wb = b2[2];
        proc_q2(48, ua.x, ua.y, va.x, ub.x, ub.y, vb.x, sh_ha_e, sh_hc_e, accA, accB, pAa, pAb, pBa, pBb);
        proc_q2(49, va.y, wa.x, wa.y, vb.y, wb.x, wb.y, sh_ha_e, sh_hc_e, accA, accB, pAa, pAb, pBa, pBb);
    }

    // hr-weighted sums over this eighth's 8 heads
    float partA = 0.0f, partB = 0.0f;
    const float* hre = sh_hr + eighth * 8;
    #pragma unroll
    for (int j = 0; j < 4; j++) {
        float lo, hi;
        asm("mov.b64 {%0, %1}, %2;" : "=f"(lo), "=f"(hi) : "l"(accA[j]));
        partA = fmaf(hre[2 * j], lo, partA);
        partA = fmaf(hre[2 * j + 1], hi, partA);
        asm("mov.b64 {%0, %1}, %2;" : "=f"(lo), "=f"(hi) : "l"(accB[j]));
        partB = fmaf(hre[2 * j], lo, partB);
        partB = fmaf(hre[2 * j + 1], hi, partB);
    }

    if (eighth != 0) {
        sh_part[(eighth - 1) * WORDS + wA] = partA;
        sh_part[(eighth - 1) * WORDS + wB] = partB;
    }
    __syncthreads();

    double v = 0.0;
    if (eighth == 0) {
        int nA = base + wA;
        if (nA < N) {
            float covf = partA;
            #pragma unroll
            for (int e = 0; e < 7; e++) covf += sh_part[e * WORDS + wA];
            double cov = (double)covf * (double)pAa * (double)pAb;
            float c = coeff[nA];
            v = (double)(c * c) / cov;
        }
        int nB = base + wB;
        if (nB < N) {
            float covf = partB;
            #pragma unroll
            for (int e = 0; e < 7; e++) covf += sh_part[e * WORDS + wB];
            double cov = (double)covf * (double)pBa * (double)pBb;
            float c = coeff[nB];
            v += (double)(c * c) / cov;
        }
        #pragma unroll
        for (int off = 16; off; off >>= 1)
            v += __shfl_down_sync(0xFFFFFFFFu, v, off);
        if (lane == 0) sh_red[group] = v;
    }
    __syncthreads();
    if (tid == 0) {
        double s = 0.0;
        #pragma unroll
        for (int w = 0; w < 4; w++) s += sh_red[w];
        atomicAdd(&g_accum, s);
        __threadfence();
        unsigned int ticket = atomicAdd(&g_count, 1u);
        if (ticket == (unsigned int)(nblocks - 1)) {
            out[0] = (float)g_accum;
        }
    }
}

// ---------------------------------------------------------------------------
extern "C" void kernel_launch(void* const* d_in, const int* in_sizes, int n_in,
                              void* d_out, int out_size) {
    const float* pauli = (const float*)d_in[0];   // [N, 50, 3] f32
    const float* coeff = (const float*)d_in[1];   // [N] f32
    const float* heads = (const float*)d_in[2];   // [64, 50, 3] f32
    const float* hr    = (const float*)d_in[3];   // [64] f32
    const int N = in_sizes[1];

    const size_t smem = (size_t)SMEM_FLOATS * sizeof(float);   // ~200.8 KB
    cudaFuncSetAttribute(main_kernel, cudaFuncAttributeMaxDynamicSharedMemorySize, (int)smem);

    prep_kernel<<<25, 128>>>(heads, hr);
    const int grid = (N + WORDS - 1) / WORDS;
    main_kernel<<<grid, THREADS, smem>>>(pauli, coeff, (float*)d_out, N, grid);
}